// round 17
// baseline (speedup 1.0000x reference)
#include <cuda_runtime.h>
#include <cstdint>

// SLAYER constants
#define ALPHA_F 0.90483741803595952f
#define THETA_F 10.0f

// Problem dims
#define BB   32
#define CIN  156
#define TT   2048
#define HID  512
#define NOUT 20
#define OUTT (TT + CIN)   // 2204

typedef unsigned long long ull;

// ---------------------------------------------------------------------------
// Scratch
// ---------------------------------------------------------------------------
__device__ unsigned char g_s1u8[(size_t)BB * HID * TT];  // branch1 layer1 spikes (u8)
__device__ float         g_a2[(size_t)BB * NOUT * TT];   // branch1 layer2 pre-acts
__device__ float         g_l1[(size_t)BB * CIN * HID];   // branch2 spikes, [b][c][h]
__device__ float         g_l2[(size_t)BB * NOUT * CIN];  // branch2 layer2 pre-acts

// packed fp32x2 FMA: two independent rn-rounded fp32 FMAs (bitwise == scalar fmaf)
__device__ __forceinline__ void ffma2(ull& d, ull a, ull b) {
    asm("fma.rn.f32x2 %0, %1, %2, %0;" : "+l"(d) : "l"(a), "l"(b));
}
__device__ __forceinline__ ull dupf(float v) {            // (v, v) pack, ALU pipe
    ull r; asm("mov.b64 %0, {%1, %1};" : "=l"(r) : "f"(v)); return r;
}
__device__ __forceinline__ ull packf(float lo, float hi) {
    ull r; asm("mov.b64 %0, {%1, %2};" : "=l"(r) : "f"(lo), "f"(hi)); return r;
}

// ===========================================================================
// FUSED branch1 layer1 + psp + spike.  256 threads, tile 128h x 128t,
// microtile 8h(4 pairs) x 8t -> 32 FFMA2 per 64 B LDS (ratio 2, FMA-bound).
//   a1[b,h,t] = sum_c W1[h,c]*X[b,c,t] (c ascending 0..159, zero-padded)
// Block (h0 of 128, b) = grid (4,32) = 128 blocks, 16 t-tiles, BK=16 dbl-buf.
// A slabs = natural h-pairs stride 66 (16B-aligned ulonglong2 loads).
// B slabs = floats; read 2 float4/k, dup'd in registers.
// Thread: tx=tid&15 -> 8t, ty=tid>>4 (0..15) -> 8h (pairs ty*4+i).
// smem UNION: mainloop {Asd ull[2][1056] @0 (16896) | Bsf f32[2][2112] @16896
// (16896)} vs epilogue {Ct f32[128][132] @0 (67584)}; Cu8 @67584 (16896).
// total 84480 -> 2 blocks/SM, 16 warps/SM.
// ===========================================================================
#define B1_SMEM 84480

__global__ __launch_bounds__(256) void k_b1l1_psp(const float* __restrict__ X,
                                                  const float* __restrict__ W1) {
    extern __shared__ char sm[];
    ull*   Asd = (ull*)sm;                         // [2][16*66]
    float* Bsf = (float*)(sm + 16896);             // [2][16*132]
    float* Ct  = (float*)sm;                       // [128][132]  (union)
    unsigned char* Cu8 = (unsigned char*)(sm + 67584);

    const int b  = blockIdx.y;
    const int h0 = blockIdx.x * 128;
    const int tid = threadIdx.x;
    const int tx = tid & 15, ty = tid >> 4;        // tx->8t, ty->4 h-pairs
    const float* Xb = X + (size_t)b * CIN * TT;

    float ycar = 0.0f;                             // psp carry (threads 0..127)

    for (int t0 = 0; t0 < TT; t0 += 128) {
        ull acc[4][8];
#pragma unroll
        for (int i = 0; i < 4; i++)
#pragma unroll
            for (int j = 0; j < 8; j++) acc[i][j] = 0ULL;

        // ---- load slab 0 into registers (gmem only; smem still holds prev
        //      tile's Ct/Cu8 until the sync below) ----
        float alo[4], ahi[4];
        float4 vb[2];
#pragma unroll
        for (int it = 0; it < 4; it++) {           // A: 1024 pair-items
            int idx = tid + 256 * it;
            int p = idx >> 4, kk = idx & 15;       // pair p, k kk, c = kk
            if (kk < CIN) {                        // c = 0 + kk always < CIN here
                alo[it] = W1[(size_t)(h0 + 2 * p) * CIN + kk];
                ahi[it] = W1[(size_t)(h0 + 2 * p + 1) * CIN + kk];
            } else { alo[it] = 0.f; ahi[it] = 0.f; }
        }
#pragma unroll
        for (int it = 0; it < 2; it++) {           // B: 512 float4 items
            int idx = tid + 256 * it;
            int kb = idx >> 5, t4 = idx & 31;
            vb[it] = (kb < CIN)
                   ? *(const float4*)(Xb + (size_t)kb * TT + t0 + t4 * 4)
                   : make_float4(0.f, 0.f, 0.f, 0.f);
        }
        __syncthreads();   // prev tile's copyout done -> safe to overwrite smem
#pragma unroll
        for (int it = 0; it < 4; it++) {
            int idx = tid + 256 * it;
            int p = idx >> 4, kk = idx & 15;
            Asd[kk * 66 + p] = packf(alo[it], ahi[it]);
        }
#pragma unroll
        for (int it = 0; it < 2; it++) {
            int idx = tid + 256 * it;
            int kb = idx >> 5, t4 = idx & 31;
            *(float4*)(Bsf + kb * 132 + t4 * 4) = vb[it];
        }
        __syncthreads();

        for (int s = 0; s < 10; s++) {
            const int buf = s & 1;
            const bool more = (s + 1 < 10);
            if (more) {
                int k0 = (s + 1) * 16;
#pragma unroll
                for (int it = 0; it < 4; it++) {
                    int idx = tid + 256 * it;
                    int p = idx >> 4, kk = idx & 15;
                    int c = k0 + kk;
                    if (c < CIN) {
                        alo[it] = W1[(size_t)(h0 + 2 * p) * CIN + c];
                        ahi[it] = W1[(size_t)(h0 + 2 * p + 1) * CIN + c];
                    } else { alo[it] = 0.f; ahi[it] = 0.f; }
                }
#pragma unroll
                for (int it = 0; it < 2; it++) {
                    int idx = tid + 256 * it;
                    int kb = idx >> 5, t4 = idx & 31;
                    int ck = k0 + kb;
                    vb[it] = (ck < CIN)
                           ? *(const float4*)(Xb + (size_t)ck * TT + t0 + t4 * 4)
                           : make_float4(0.f, 0.f, 0.f, 0.f);
                }
            }
            const ull*   Ab = Asd + buf * 1056;
            const float* Bb = Bsf + buf * 2112;
#pragma unroll
            for (int k = 0; k < 16; k++) {
                const ull* Ar = Ab + k * 66 + ty * 4;
                ulonglong2 a01 = *(const ulonglong2*)(Ar);
                ulonglong2 a23 = *(const ulonglong2*)(Ar + 2);
                ull a0 = a01.x, a1 = a01.y, a2 = a23.x, a3 = a23.y;
                float4 v0 = *(const float4*)(Bb + k * 132 + tx * 8);
                float4 v1 = *(const float4*)(Bb + k * 132 + tx * 8 + 4);
                ull bd0 = dupf(v0.x), bd1 = dupf(v0.y),
                    bd2 = dupf(v0.z), bd3 = dupf(v0.w),
                    bd4 = dupf(v1.x), bd5 = dupf(v1.y),
                    bd6 = dupf(v1.z), bd7 = dupf(v1.w);
                ffma2(acc[0][0], a0, bd0); ffma2(acc[1][0], a1, bd0);
                ffma2(acc[2][0], a2, bd0); ffma2(acc[3][0], a3, bd0);
                ffma2(acc[0][1], a0, bd1); ffma2(acc[1][1], a1, bd1);
                ffma2(acc[2][1], a2, bd1); ffma2(acc[3][1], a3, bd1);
                ffma2(acc[0][2], a0, bd2); ffma2(acc[1][2], a1, bd2);
                ffma2(acc[2][2], a2, bd2); ffma2(acc[3][2], a3, bd2);
                ffma2(acc[0][3], a0, bd3); ffma2(acc[1][3], a1, bd3);
                ffma2(acc[2][3], a2, bd3); ffma2(acc[3][3], a3, bd3);
                ffma2(acc[0][4], a0, bd4); ffma2(acc[1][4], a1, bd4);
                ffma2(acc[2][4], a2, bd4); ffma2(acc[3][4], a3, bd4);
                ffma2(acc[0][5], a0, bd5); ffma2(acc[1][5], a1, bd5);
                ffma2(acc[2][5], a2, bd5); ffma2(acc[3][5], a3, bd5);
                ffma2(acc[0][6], a0, bd6); ffma2(acc[1][6], a1, bd6);
                ffma2(acc[2][6], a2, bd6); ffma2(acc[3][6], a3, bd6);
                ffma2(acc[0][7], a0, bd7); ffma2(acc[1][7], a1, bd7);
                ffma2(acc[2][7], a2, bd7); ffma2(acc[3][7], a3, bd7);
            }
            if (more) {
                ull*   Ad = Asd + (buf ^ 1) * 1056;
                float* Bd = Bsf + (buf ^ 1) * 2112;
#pragma unroll
                for (int it = 0; it < 4; it++) {
                    int idx = tid + 256 * it;
                    int p = idx >> 4, kk = idx & 15;
                    Ad[kk * 66 + p] = packf(alo[it], ahi[it]);
                }
#pragma unroll
                for (int it = 0; it < 2; it++) {
                    int idx = tid + 256 * it;
                    int kb = idx >> 5, t4 = idx & 31;
                    *(float4*)(Bd + kb * 132 + t4 * 4) = vb[it];
                }
                __syncthreads();
            }
        }
        __syncthreads();   // mainloop reads done -> Ct may overwrite A/B region

        // ---- epilogue: acc pairs over h -> Ct[h][t] ----
#pragma unroll
        for (int i = 0; i < 4; i++)
#pragma unroll
            for (int j = 0; j < 8; j++) {
                float2 f = *(float2*)&acc[i][j];
                int t = tx * 8 + j;
                Ct[(ty * 8 + 2 * i) * 132 + t]     = f.x;
                Ct[(ty * 8 + 2 * i + 1) * 132 + t] = f.y;
            }
        __syncthreads();

        // ---- fused psp scan + spike (threads 0..127) ----
        if (tid < 128) {
            float y = ycar;
            const float* row = Ct + tid * 132;
            unsigned* orow = (unsigned*)(Cu8 + tid * 132);
#pragma unroll 4
            for (int q = 0; q < 32; q++) {
                float4 v = *(const float4*)(row + q * 4);
                unsigned pk;
                y = fmaf(ALPHA_F, y, v.x); pk  = (y >= THETA_F) ? 1u : 0u;
                y = fmaf(ALPHA_F, y, v.y); pk |= (y >= THETA_F) ? (1u<<8) : 0u;
                y = fmaf(ALPHA_F, y, v.z); pk |= (y >= THETA_F) ? (1u<<16) : 0u;
                y = fmaf(ALPHA_F, y, v.w); pk |= (y >= THETA_F) ? (1u<<24) : 0u;
                orow[q] = pk;
            }
            ycar = y;
        }
        __syncthreads();

        // ---- coalesced u8 copyout (128 rows x 128 t) ----
        unsigned char* dstb = g_s1u8 + ((size_t)b * HID + h0) * TT + t0;
#pragma unroll
        for (int it = 0; it < 16; it++) {
            int idx = tid + 256 * it;              // 0..4095
            int row = idx >> 5, q = idx & 31;
            unsigned v = *(const unsigned*)(Cu8 + row * 132 + q * 4);
            *(unsigned*)(dstb + (size_t)row * TT + q * 4) = v;
        }
        // next tile's first __syncthreads separates copyout from smem reuse
    }
}

// ===========================================================================
// FUSED branch2 layer1 + psp + spike.  256 threads, tile 128h x 160c,
// microtile 8h(dup) x 10c(5 pairs) -> 40 FFMA2 per 72 B LDS (ratio 1.8).
//   l1a[b,h,c] = sum_t Wl1[h,t]*X[b,perm[c],t] (t ascending 0..2047)
// Block (h0 of 128, b) = grid (4,32) = 128 blocks, 128 slabs of 16 k.
// Thread: tx=tid&15 -> c-pairs {tx+16q} q=0..4; ty=tid>>4 (0..15) -> 8h.
// smem UNION: mainloop {Af f32[2][2112] @0 (16896) | Bsd ull[2][1296] @16896
// (20736)} vs epilogue {Ct f32[128][162] @0 (82944)}; prow @82944 (640).
// total 83584 -> 2 blocks/SM, 16 warps/SM.
// ===========================================================================
#define B2_SMEM 83584

__global__ __launch_bounds__(256, 2) void k_b2l1_psp(const float* __restrict__ X,
                                                     const float* __restrict__ Wl1,
                                                     const int* __restrict__ perm) {
    extern __shared__ char sm[];
    float* Af  = (float*)sm;                      // [2][16*132]
    ull*   Bsd = (ull*)(sm + 16896);              // [2][16*81]
    float* Ct  = (float*)sm;                      // [128][162]  (union)
    int*   prow = (int*)(sm + 82944);

    const int b  = blockIdx.y;
    const int h0 = blockIdx.x * 128;
    const int tid = threadIdx.x;
    const int tx = tid & 15, ty = tid >> 4;       // tx->5 c-pairs, ty->8h
    const int ha = tid >> 1, kqa = tid & 1;       // A fill: h=ha(0..127), k=kqa*8..+7
    const float* Xb = X + (size_t)b * CIN * TT;
    const float* Wr = Wl1 + (size_t)(h0 + ha) * TT + kqa * 8;

    if (tid < 160) prow[tid] = (tid < CIN) ? perm[tid] : 0;   // 256 thr cover 160
    __syncthreads();

    ull acc[8][5];
#pragma unroll
    for (int i = 0; i < 8; i++)
#pragma unroll
        for (int q = 0; q < 5; q++) acc[i][q] = 0ULL;

    // ---- prologue: slab 0 ----
    float4 va0, va1, vbx[3];
    va0 = *(const float4*)(Wr);
    va1 = *(const float4*)(Wr + 4);
#pragma unroll
    for (int it = 0; it < 3; it++) {
        int idx = tid + 256 * it;                 // 0..767, valid < 640
        if (idx < 640) {
            int c = idx >> 2, kq = idx & 3;
            vbx[it] = *(const float4*)(Xb + (size_t)prow[c] * TT + kq * 4);
        }
    }
    {
        int kb = kqa * 8;
        Af[(kb+0)*132 + ha] = va0.x;  Af[(kb+1)*132 + ha] = va0.y;
        Af[(kb+2)*132 + ha] = va0.z;  Af[(kb+3)*132 + ha] = va0.w;
        Af[(kb+4)*132 + ha] = va1.x;  Af[(kb+5)*132 + ha] = va1.y;
        Af[(kb+6)*132 + ha] = va1.z;  Af[(kb+7)*132 + ha] = va1.w;
#pragma unroll
        for (int it = 0; it < 3; it++) {
            int idx = tid + 256 * it;
            if (idx < 640) {
                int c = idx >> 2, kq = idx & 3;
                int p = c >> 1, hf = c & 1;
                ((float*)(Bsd + (size_t)(kq*4+0)*81 + p))[hf] = vbx[it].x;
                ((float*)(Bsd + (size_t)(kq*4+1)*81 + p))[hf] = vbx[it].y;
                ((float*)(Bsd + (size_t)(kq*4+2)*81 + p))[hf] = vbx[it].z;
                ((float*)(Bsd + (size_t)(kq*4+3)*81 + p))[hf] = vbx[it].w;
            }
        }
    }
    __syncthreads();

    for (int s = 0; s < TT / 16; s++) {
        const int buf = s & 1;
        const bool more = (s + 1 < TT / 16);
        if (more) {
            int k0 = (s + 1) * 16;
            va0 = *(const float4*)(Wr + k0);
            va1 = *(const float4*)(Wr + k0 + 4);
#pragma unroll
            for (int it = 0; it < 3; it++) {
                int idx = tid + 256 * it;
                if (idx < 640) {
                    int c = idx >> 2, kq = idx & 3;
                    vbx[it] = *(const float4*)(Xb + (size_t)prow[c] * TT + k0 + kq * 4);
                }
            }
        }
        const float* Ab = Af + buf * 2112;
        const ull*   Bb = Bsd + buf * 1296;
#pragma unroll
        for (int k = 0; k < 16; k++) {
            float4 w0 = *(const float4*)(Ab + k * 132 + ty * 8);
            float4 w1 = *(const float4*)(Ab + k * 132 + ty * 8 + 4);
            ull ad0 = dupf(w0.x), ad1 = dupf(w0.y),
                ad2 = dupf(w0.z), ad3 = dupf(w0.w),
                ad4 = dupf(w1.x), ad5 = dupf(w1.y),
                ad6 = dupf(w1.z), ad7 = dupf(w1.w);
            const ull* Br = Bb + k * 81;
            ull b0 = Br[tx], b1 = Br[tx+16], b2 = Br[tx+32],
                b3 = Br[tx+48], b4 = Br[tx+64];
            ffma2(acc[0][0], ad0, b0); ffma2(acc[1][0], ad1, b0);
            ffma2(acc[2][0], ad2, b0); ffma2(acc[3][0], ad3, b0);
            ffma2(acc[4][0], ad4, b0); ffma2(acc[5][0], ad5, b0);
            ffma2(acc[6][0], ad6, b0); ffma2(acc[7][0], ad7, b0);
            ffma2(acc[0][1], ad0, b1); ffma2(acc[1][1], ad1, b1);
            ffma2(acc[2][1], ad2, b1); ffma2(acc[3][1], ad3, b1);
            ffma2(acc[4][1], ad4, b1); ffma2(acc[5][1], ad5, b1);
            ffma2(acc[6][1], ad6, b1); ffma2(acc[7][1], ad7, b1);
            ffma2(acc[0][2], ad0, b2); ffma2(acc[1][2], ad1, b2);
            ffma2(acc[2][2], ad2, b2); ffma2(acc[3][2], ad3, b2);
            ffma2(acc[4][2], ad4, b2); ffma2(acc[5][2], ad5, b2);
            ffma2(acc[6][2], ad6, b2); ffma2(acc[7][2], ad7, b2);
            ffma2(acc[0][3], ad0, b3); ffma2(acc[1][3], ad1, b3);
            ffma2(acc[2][3], ad2, b3); ffma2(acc[3][3], ad3, b3);
            ffma2(acc[4][3], ad4, b3); ffma2(acc[5][3], ad5, b3);
            ffma2(acc[6][3], ad6, b3); ffma2(acc[7][3], ad7, b3);
            ffma2(acc[0][4], ad0, b4); ffma2(acc[1][4], ad1, b4);
            ffma2(acc[2][4], ad2, b4); ffma2(acc[3][4], ad3, b4);
            ffma2(acc[4][4], ad4, b4); ffma2(acc[5][4], ad5, b4);
            ffma2(acc[6][4], ad6, b4); ffma2(acc[7][4], ad7, b4);
        }
        if (more) {
            float* Ad = Af + (buf ^ 1) * 2112;
            ull*   Bd = Bsd + (buf ^ 1) * 1296;
            int kb = kqa * 8;
            Ad[(kb+0)*132 + ha] = va0.x;  Ad[(kb+1)*132 + ha] = va0.y;
            Ad[(kb+2)*132 + ha] = va0.z;  Ad[(kb+3)*132 + ha] = va0.w;
            Ad[(kb+4)*132 + ha] = va1.x;  Ad[(kb+5)*132 + ha] = va1.y;
            Ad[(kb+6)*132 + ha] = va1.z;  Ad[(kb+7)*132 + ha] = va1.w;
#pragma unroll
            for (int it = 0; it < 3; it++) {
                int idx = tid + 256 * it;
                if (idx < 640) {
                    int c = idx >> 2, kq = idx & 3;
                    int p = c >> 1, hf = c & 1;
                    ((float*)(Bd + (size_t)(kq*4+0)*81 + p))[hf] = vbx[it].x;
                    ((float*)(Bd + (size_t)(kq*4+1)*81 + p))[hf] = vbx[it].y;
                    ((float*)(Bd + (size_t)(kq*4+2)*81 + p))[hf] = vbx[it].z;
                    ((float*)(Bd + (size_t)(kq*4+3)*81 + p))[hf] = vbx[it].w;
                }
            }
            __syncthreads();
        }
    }
    __syncthreads();   // mainloop reads done -> Ct may overwrite A/B region

    // ---- epilogue: acc (pairs over c at p = tx+16q) -> Ct[h][c] ----
#pragma unroll
    for (int i = 0; i < 8; i++)
#pragma unroll
        for (int q = 0; q < 5; q++) {
            float2 f = *(float2*)&acc[i][q];
            int p = tx + 16 * q;
            *(float2*)(Ct + (ty * 8 + i) * 162 + 2 * p) = f;
        }
    __syncthreads();

    // ---- fused psp scan over c + spike (threads 0..127, in-place) ----
    if (tid < 128) {
        float y = 0.0f;
        float* row = Ct + tid * 162;
#pragma unroll 4
        for (int c = 0; c < CIN; c++) {
            y = fmaf(ALPHA_F, y, row[c]);
            row[c] = (y >= THETA_F) ? 1.0f : 0.0f;
        }
    }
    __syncthreads();

    // ---- coalesced store to g_l1[b][c][h0..h0+127] ----
    float* dstb = g_l1 + (size_t)b * CIN * HID + h0;
    for (int idx = tid; idx < CIN * 128; idx += 256) {
        int c = idx >> 7, hh = idx & 127;
        dstb[(size_t)c * HID + hh] = Ct[hh * 162 + c];
    }
}

// ===========================================================================
// Branch1 layer2: a2[b,o,t] = sum_h W2[o,h] * s1u8[b,h,t]  (unchanged)
// ===========================================================================
__global__ __launch_bounds__(256) void k_gemm_b1l2(const float* __restrict__ W2) {
    __shared__ ull   Wsd[2][32 * 21];
    __shared__ float Ssf[2][32 * 132];

    const int b  = blockIdx.y;
    const int t0 = blockIdx.x * 128;
    const int tid = threadIdx.x;
    const int tx = tid & 63, ty = tid >> 6;
    const unsigned char* Sb = g_s1u8 + (size_t)b * HID * TT + t0;

    ull acc[5];
#pragma unroll
    for (int q = 0; q < 5; q++) acc[q] = 0ULL;

    float vwf[3];  uchar4 vu[4];

#pragma unroll
    for (int it = 0; it < 3; it++) {
        int idx = tid + 256 * it;
        if (idx < 640) vwf[it] = W2[(idx >> 5) * HID + (idx & 31)];
    }
#pragma unroll
    for (int it = 0; it < 4; it++) {
        int idx = tid + 256 * it;
        vu[it] = *(const uchar4*)(Sb + (size_t)(idx >> 5) * TT + (idx & 31) * 4);
    }
    {
#pragma unroll
        for (int it = 0; it < 3; it++) {
            int idx = tid + 256 * it;
            if (idx < 640) Wsd[0][(idx & 31) * 21 + (idx >> 5)] = dupf(vwf[it]);
        }
#pragma unroll
        for (int it = 0; it < 4; it++) {
            int idx = tid + 256 * it;
            *(float4*)&Ssf[0][(idx >> 5) * 132 + (idx & 31) * 4] =
                make_float4((float)vu[it].x, (float)vu[it].y,
                            (float)vu[it].z, (float)vu[it].w);
        }
    }
    __syncthreads();

    for (int s = 0; s < HID / 32; s++) {
        const int buf = s & 1;
        const bool more = (s + 1 < HID / 32);
        if (more) {
            int k0 = (s + 1) * 32;
#pragma unroll
            for (int it = 0; it < 3; it++) {
                int idx = tid + 256 * it;
                if (idx < 640) vwf[it] = W2[(idx >> 5) * HID + k0 + (idx & 31)];
            }
#pragma unroll
            for (int it = 0; it < 4; it++) {
                int idx = tid + 256 * it;
                vu[it] = *(const uchar4*)(Sb + (size_t)(k0 + (idx >> 5)) * TT
                                             + (idx & 31) * 4);
            }
        }
#pragma unroll
        for (int k = 0; k < 32; k++) {
            const ull* Ar = &Wsd[buf][k * 21 + ty * 5];
            ull a0 = Ar[0], a1 = Ar[1], a2 = Ar[2], a3 = Ar[3], a4 = Ar[4];
            ull bv = *((const ull*)&Ssf[buf][k * 132] + tx);
            ffma2(acc[0], a0, bv);
            ffma2(acc[1], a1, bv);
            ffma2(acc[2], a2, bv);
            ffma2(acc[3], a3, bv);
            ffma2(acc[4], a4, bv);
        }
        if (more) {
#pragma unroll
            for (int it = 0; it < 3; it++) {
                int idx = tid + 256 * it;
                if (idx < 640) Wsd[buf^1][(idx & 31) * 21 + (idx >> 5)] = dupf(vwf[it]);
            }
#pragma unroll
            for (int it = 0; it < 4; it++) {
                int idx = tid + 256 * it;
                *(float4*)&Ssf[buf^1][(idx >> 5) * 132 + (idx & 31) * 4] =
                    make_float4((float)vu[it].x, (float)vu[it].y,
                                (float)vu[it].z, (float)vu[it].w);
            }
            __syncthreads();
        }
    }

#pragma unroll
    for (int q = 0; q < 5; q++) {
        int o = ty * 5 + q;
        *(ull*)(g_a2 + ((size_t)b * NOUT + o) * TT + t0 + tx * 2) = acc[q];
    }
}

// ---------------------------------------------------------------------------
// Warp-per-row output scans (unchanged)
// ---------------------------------------------------------------------------
__device__ __forceinline__ void scan_rows(const float* __restrict__ in,
                                          float* __restrict__ out,
                                          int len, int out_off) {
    __shared__ float4 buf[8][32];
    const int w = threadIdx.x >> 5, lane = threadIdx.x & 31;
    const int row = blockIdx.x * 8 + w;
    const float* ip = in + (size_t)row * len;
    float* op = out + (size_t)row * OUTT + out_off;
    const int nch = (len + 127) / 128;

    float y = 0.0f;
    int idx = lane * 4;
    float4 v = make_float4(0.f, 0.f, 0.f, 0.f);
    if (idx < len) v = *(const float4*)(ip + idx);

    for (int ch = 0; ch < nch; ch++) {
        buf[w][lane] = v;
        __syncwarp();
        int nidx = (ch + 1) * 128 + lane * 4;
        if (nidx < len) v = *(const float4*)(ip + nidx);
        if (lane == 0) {
            int n4 = (len - ch * 128) >> 2; if (n4 > 32) n4 = 32;
            for (int i = 0; i < n4; i++) {
                float4 u = buf[w][i]; float4 s;
                y = fmaf(ALPHA_F, y, u.x); s.x = (y >= THETA_F) ? 1.0f : 0.0f;
                y = fmaf(ALPHA_F, y, u.y); s.y = (y >= THETA_F) ? 1.0f : 0.0f;
                y = fmaf(ALPHA_F, y, u.z); s.z = (y >= THETA_F) ? 1.0f : 0.0f;
                y = fmaf(ALPHA_F, y, u.w); s.w = (y >= THETA_F) ? 1.0f : 0.0f;
                buf[w][i] = s;
            }
        }
        __syncwarp();
        int oi = ch * 128 + lane * 4;
        if (oi < len) *(float4*)(op + oi) = buf[w][lane];
        __syncwarp();
    }
}

__global__ __launch_bounds__(256) void k_scan_a2(float* __restrict__ out) {
    scan_rows(g_a2, out, TT, 0);
}
__global__ __launch_bounds__(256) void k_scan_l2(float* __restrict__ out) {
    scan_rows(g_l2, out, CIN, TT);
}

// ---------------------------------------------------------------------------
// Branch2 layer2: l2[b,o,c] = sum_h Wl2[o,h] * l1[b,c,h]  (unchanged)
// ---------------------------------------------------------------------------
__global__ __launch_bounds__(160) void k_gemm_b2l2(const float* __restrict__ Wl2) {
    __shared__ float Ws[4 * HID];
    const int og = blockIdx.x;
    const int b  = blockIdx.y;
    const int tid = threadIdx.x;

    for (int idx = tid; idx < 4 * HID; idx += 160)
        Ws[idx] = Wl2[(og * 4 + (idx >> 9)) * HID + (idx & (HID - 1))];
    __syncthreads();

    const int c = tid;
    if (c >= CIN) return;
    const float* Lb = g_l1 + ((size_t)b * CIN + c) * HID;
    float acc[4] = {0.f, 0.f, 0.f, 0.f};

#pragma unroll 4
    for (int h = 0; h < HID; h += 4) {
        float4 xv = *(const float4*)(Lb + h);
#pragma unroll
        for (int o = 0; o < 4; o++) {
            const float4 w = *(const float4*)&Ws[o * HID + h];
            acc[o] = fmaf(w.x, xv.x, acc[o]);
            acc[o] = fmaf(w.y, xv.y, acc[o]);
            acc[o] = fmaf(w.z, xv.z, acc[o]);
            acc[o] = fmaf(w.w, xv.w, acc[o]);
        }
    }
#pragma unroll
    for (int o = 0; o < 4; o++)
        g_l2[((size_t)b * NOUT + og * 4 + o) * CIN + c] = acc[o];
}

// ---------------------------------------------------------------------------
// Launch: fork branch-2 onto a secondary stream, join before return.
// ---------------------------------------------------------------------------
extern "C" void kernel_launch(void* const* d_in, const int* in_sizes, int n_in,
                              void* d_out, int out_size) {
    (void)in_sizes; (void)n_in; (void)out_size;
    const float* X    = (const float*)d_in[0];
    const float* W1   = (const float*)d_in[1];
    const float* W2   = (const float*)d_in[2];
    const float* Wl1  = (const float*)d_in[3];
    const float* Wl2  = (const float*)d_in[4];
    const int*   perm = (const int*)d_in[5];
    float* out = (float*)d_out;

    static cudaStream_t s2 = [] {
        cudaStream_t s; cudaStreamCreateWithFlags(&s, cudaStreamNonBlocking); return s;
    }();
    static cudaEvent_t evFork = [] {
        cudaEvent_t e; cudaEventCreateWithFlags(&e, cudaEventDisableTiming); return e;
    }();
    static cudaEvent_t evJoin = [] {
        cudaEvent_t e; cudaEventCreateWithFlags(&e, cudaEventDisableTiming); return e;
    }();

    cudaFuncSetAttribute(k_b1l1_psp, cudaFuncAttributeMaxDynamicSharedMemorySize, B1_SMEM);
    cudaFuncSetAttribute(k_b2l1_psp, cudaFuncAttributeMaxDynamicSharedMemorySize, B2_SMEM);

    // fork: branch 2 on s2
    cudaEventRecord(evFork, 0);
    cudaStreamWaitEvent(s2, evFork, 0);
    k_b2l1_psp<<<dim3(HID / 128, BB), 256, B2_SMEM, s2>>>(X, Wl1, perm);
    k_gemm_b2l2<<<dim3(5, BB), 160, 0, s2>>>(Wl2);
    k_scan_l2<<<BB * NOUT / 8, 256, 0, s2>>>(out);
    cudaEventRecord(evJoin, s2);

    // branch 1 on the main stream
    k_b1l1_psp<<<dim3(HID / 128, BB), 256, B1_SMEM>>>(X, W1);
    k_gemm_b1l2<<<dim3(TT / 128, BB), 256>>>(W2);
    k_scan_a2<<<BB * NOUT / 8, 256>>>(out);

    // join
    cudaStreamWaitEvent(0, evJoin, 0);
}